// round 4
// baseline (speedup 1.0000x reference)
#include <cuda_runtime.h>
#include <cuda_bf16.h>
#include <math.h>

// Problem constants
#define NN   100000
#define FEAT 64
#define HID  128
#define EE   3200000
#define NP   3
#define ALPHA 0.1f

// ---------------- device scratch (static allocation; no cudaMalloc) ----------------
__device__ __align__(16) float g_x[NN * FEAT];      // relu(h), also feat0
__device__ __align__(16) float g_z0[NN * FEAT];     // per-path final features
__device__ __align__(16) float g_z1[NN * FEAT];
__device__ __align__(16) float g_z2[NN * FEAT];
__device__ __align__(16) float g_featS[NN * FEAT];  // feat pre-scaled by norm_out
__device__ __align__(16) float g_agg[NN * FEAT];    // scatter accumulator (kept zeroed)
__device__ int   g_src32[NP * EE];
__device__ int   g_dst32[NP * EE];
__device__ int   g_deg_out[NP * NN];
__device__ int   g_deg_in[NP * NN];
__device__ float g_norm_out[NP * NN];
__device__ float g_norm_in[NP * NN];
__device__ float g_wsum[NP];
__device__ float g_beta[NP];
__device__ int   g_is64;

__device__ __forceinline__ float* zbuf(int p) {
    return p == 0 ? g_z0 : (p == 1 ? g_z1 : g_z2);
}

// ---------------- kernels ----------------

// Detect whether index buffers are int64 or int32.
// If the data is int32, an int64-read packs two indices -> high word nonzero
// (probability of false positive over 64 reads is ~(1e-5)^64, i.e. zero).
__global__ void k_detect(const void* __restrict__ src) {
    const long long* s64 = (const long long*)src;
    int ok = 1;
    for (int i = 0; i < 64; i++) {
        long long v = s64[i];
        if (v < 0 || v >= NN) { ok = 0; break; }
    }
    g_is64 = ok;
}

// x = relu(h); zero agg, degrees, wsum
__global__ void k_init(const float* __restrict__ h) {
    int i = blockIdx.x * blockDim.x + threadIdx.x;
    if (i < NN * FEAT) {
        g_x[i]   = fmaxf(h[i], 0.0f);
        g_agg[i] = 0.0f;
    }
    if (i < NP * NN) {
        g_deg_out[i] = 0;
        g_deg_in[i]  = 0;
    }
    if (i < NP) g_wsum[i] = 0.0f;
}

// index conversion (int64 or int32 -> int32, clamped) + degree histograms
__global__ void k_degcvt(const void* __restrict__ src,
                         const void* __restrict__ dst) {
    int i = blockIdx.x * blockDim.x + threadIdx.x;
    if (i >= NP * EE) return;
    int p = i / EE;
    long long sv, dv;
    if (g_is64) {
        sv = ((const long long*)src)[i];
        dv = ((const long long*)dst)[i];
    } else {
        sv = ((const int*)src)[i];
        dv = ((const int*)dst)[i];
    }
    int s = (int)sv; if (s < 0) s = 0; if (s >= NN) s = NN - 1;
    int d = (int)dv; if (d < 0) d = 0; if (d >= NN) d = NN - 1;
    g_src32[i] = s;
    g_dst32[i] = d;
    atomicAdd(&g_deg_out[p * NN + s], 1);
    atomicAdd(&g_deg_in[p * NN + d], 1);
}

// norm = clip(deg,1)^-0.5
__global__ void k_norm() {
    int i = blockIdx.x * blockDim.x + threadIdx.x;
    if (i >= NP * NN) return;
    int dOut = g_deg_out[i]; if (dOut < 1) dOut = 1;
    int dIn  = g_deg_in[i];  if (dIn  < 1) dIn  = 1;
    g_norm_out[i] = rsqrtf((float)dOut);
    g_norm_in[i]  = rsqrtf((float)dIn);
}

// featS = x * norm_out[p]  (start of each path)
__global__ void k_scale(int p) {
    int i = blockIdx.x * blockDim.x + threadIdx.x;
    if (i >= NN * FEAT) return;
    g_featS[i] = g_x[i] * g_norm_out[p * NN + (i >> 6)];
}

// scatter: for each edge, agg[dst] += featS[src]
// 16 threads per edge; each thread: one float4 gather + 4 scalar RED.ADD.F32
__global__ void __launch_bounds__(256) k_scatter(int p) {
    long long t = (long long)blockIdx.x * blockDim.x + threadIdx.x;
    if (t >= (long long)EE * 16) return;
    int e = (int)(t >> 4);
    int c = (int)(t & 15);
    int s = g_src32[p * EE + e];
    int d = g_dst32[p * EE + e];
    const float4* fs = (const float4*)g_featS;
    float4 v = fs[s * 16 + c];
    float* a = &g_agg[d * FEAT + c * 4];
    atomicAdd(a + 0, v.x);    // result unused -> RED.E.ADD.F32
    atomicAdd(a + 1, v.y);
    atomicAdd(a + 2, v.z);
    atomicAdd(a + 3, v.w);
}

// combine: feat = 0.9*agg*norm_in + 0.1*x ; re-zero agg ; write featS (scaled) or z[p] (last)
__global__ void k_combine(int p, int last) {
    int i = blockIdx.x * blockDim.x + threadIdx.x;   // float4 granularity: NN*16
    if (i >= NN * 16) return;
    float4* a4 = (float4*)g_agg;
    float4 a = a4[i];
    a4[i] = make_float4(0.f, 0.f, 0.f, 0.f);
    int n = i >> 4;
    float ni = g_norm_in[p * NN + n];
    const float4* x4 = (const float4*)g_x;
    float4 x = x4[i];
    float4 v;
    v.x = 0.9f * a.x * ni + ALPHA * x.x;
    v.y = 0.9f * a.y * ni + ALPHA * x.y;
    v.z = 0.9f * a.z * ni + ALPHA * x.z;
    v.w = 0.9f * a.w * ni + ALPHA * x.w;
    if (last) {
        ((float4*)zbuf(p))[i] = v;
    } else {
        float no = g_norm_out[p * NN + n];
        v.x *= no; v.y *= no; v.z *= no; v.w *= no;
        ((float4*)g_featS)[i] = v;
    }
}

// semantic fusion scores: wsum[p] += sum_n tanh(z[n,p,:]@W1 + b1) @ W2
__global__ void __launch_bounds__(256) k_fusion(const float* __restrict__ W1,
                                                const float* __restrict__ b1,
                                                const float* __restrict__ W2) {
    __shared__ float sW1[FEAT * HID];   // 32 KB, row k holds W1[k][0..127]
    __shared__ float sb1[HID];
    __shared__ float sW2[HID];
    __shared__ float sred[256];
    int tid = threadIdx.x;
    for (int i = tid; i < FEAT * HID; i += 256) sW1[i] = W1[i];
    if (tid < HID) { sb1[tid] = b1[tid]; sW2[tid] = W2[tid]; }
    __syncthreads();

    int p = blockIdx.y;
    int n = blockIdx.x * 256 + tid;
    float acc = 0.0f;
    if (n < NN) {
        float zr[FEAT];
        const float4* zp = (const float4*)zbuf(p);
        #pragma unroll
        for (int i = 0; i < 16; i++) {
            float4 v = zp[n * 16 + i];
            zr[4 * i + 0] = v.x; zr[4 * i + 1] = v.y;
            zr[4 * i + 2] = v.z; zr[4 * i + 3] = v.w;
        }
        for (int j = 0; j < HID; j += 4) {
            float h0 = sb1[j], h1 = sb1[j + 1], h2 = sb1[j + 2], h3 = sb1[j + 3];
            #pragma unroll
            for (int k = 0; k < FEAT; k++) {
                float4 w = *(const float4*)&sW1[k * HID + j];
                h0 = fmaf(zr[k], w.x, h0);
                h1 = fmaf(zr[k], w.y, h1);
                h2 = fmaf(zr[k], w.z, h2);
                h3 = fmaf(zr[k], w.w, h3);
            }
            acc += tanhf(h0) * sW2[j]     + tanhf(h1) * sW2[j + 1]
                 + tanhf(h2) * sW2[j + 2] + tanhf(h3) * sW2[j + 3];
        }
    }
    sred[tid] = acc;
    __syncthreads();
    for (int s = 128; s > 0; s >>= 1) {
        if (tid < s) sred[tid] += sred[tid + s];
        __syncthreads();
    }
    if (tid == 0) atomicAdd(&g_wsum[p], sred[0]);
}

// beta = softmax(wsum / N)
__global__ void k_softmax() {
    float w0 = g_wsum[0] / (float)NN;
    float w1 = g_wsum[1] / (float)NN;
    float w2 = g_wsum[2] / (float)NN;
    float m = fmaxf(w0, fmaxf(w1, w2));
    float e0 = expf(w0 - m), e1 = expf(w1 - m), e2 = expf(w2 - m);
    float s = e0 + e1 + e2;
    g_beta[0] = e0 / s; g_beta[1] = e1 / s; g_beta[2] = e2 / s;
}

// out = sum_p beta[p] * z[p]
__global__ void k_final(float* __restrict__ out) {
    int i = blockIdx.x * blockDim.x + threadIdx.x;   // float4 granularity
    if (i >= NN * 16) return;
    float b0 = g_beta[0], b1 = g_beta[1], b2 = g_beta[2];
    float4 a = ((const float4*)g_z0)[i];
    float4 b = ((const float4*)g_z1)[i];
    float4 c = ((const float4*)g_z2)[i];
    float4 o;
    o.x = b0 * a.x + b1 * b.x + b2 * c.x;
    o.y = b0 * a.y + b1 * b.y + b2 * c.y;
    o.z = b0 * a.z + b1 * b.z + b2 * c.z;
    o.w = b0 * a.w + b1 * b.w + b2 * c.w;
    ((float4*)out)[i] = o;
}

// ---------------- launch ----------------
extern "C" void kernel_launch(void* const* d_in, const int* in_sizes, int n_in,
                              void* d_out, int out_size) {
    const float* h   = (const float*)d_in[0];
    const void*  src = d_in[1];
    const void*  dst = d_in[2];
    const float* W1  = (const float*)d_in[3];
    const float* b1  = (const float*)d_in[4];
    const float* W2  = (const float*)d_in[5];
    float* out = (float*)d_out;

    const int TB = 256;
    int gNF  = (NN * FEAT + TB - 1) / TB;     // 6.4M threads
    int gE   = (NP * EE + TB - 1) / TB;       // 9.6M threads
    int gPN  = (NP * NN + TB - 1) / TB;
    int gV4  = (NN * 16 + TB - 1) / TB;       // float4 granularity
    long long scThreads = (long long)EE * 16; // 51.2M threads
    int gSc  = (int)((scThreads + TB - 1) / TB);

    k_detect<<<1, 1>>>(src);
    k_init<<<gNF, TB>>>(h);
    k_degcvt<<<gE, TB>>>(src, dst);
    k_norm<<<gPN, TB>>>();

    for (int p = 0; p < NP; p++) {
        k_scale<<<gNF, TB>>>(p);
        for (int k = 0; k < 3; k++) {
            k_scatter<<<gSc, TB>>>(p);
            k_combine<<<gV4, TB>>>(p, (k == 2) ? 1 : 0);
        }
    }

    dim3 gF((NN + TB - 1) / TB, NP);
    k_fusion<<<gF, TB>>>(W1, b1, W2);
    k_softmax<<<1, 1>>>();
    k_final<<<gV4, TB>>>(out);
}

// round 11
// speedup vs baseline: 3.6018x; 3.6018x over previous
#include <cuda_runtime.h>
#include <cuda_bf16.h>
#include <math.h>

// Problem constants
#define NN   100000
#define FEAT 64
#define HID  128
#define EE   3200000
#define NP   3
#define ALPHA 0.1f

// ---------------- device scratch (static allocation; no cudaMalloc) ----------------
__device__ __align__(16) float g_x[NN * FEAT];      // relu(h), also feat0
__device__ __align__(16) float g_z0[NN * FEAT];     // per-path final features
__device__ __align__(16) float g_z1[NN * FEAT];
__device__ __align__(16) float g_z2[NN * FEAT];
__device__ __align__(16) float g_fA[NN * FEAT];     // ping-pong feature buffers
__device__ __align__(16) float g_fB[NN * FEAT];     //   (pre-scaled by norm_out)
__device__ int   g_src32[NP * EE];
__device__ int   g_dst32[NP * EE];
__device__ int   g_csr[NP * EE];      // CSR: src indices grouped by dst
__device__ int   g_rowstart[NP * NN]; // CSR row offsets (per path)
__device__ int   g_fill[NP * NN];     // per-row fill counters
__device__ int   g_ecnt[NP];          // per-path edge counters for range grab
__device__ int   g_deg_out[NP * NN];
__device__ int   g_deg_in[NP * NN];
__device__ float g_norm_out[NP * NN];
__device__ float g_norm_in[NP * NN];
__device__ float g_wsum[NP];
__device__ float g_beta[NP];
__device__ int   g_is64;

__device__ __forceinline__ float* zbuf(int p) {
    return p == 0 ? g_z0 : (p == 1 ? g_z1 : g_z2);
}

// ---------------- kernels ----------------

// Detect whether index buffers are int64 or int32.
__global__ void k_detect(const void* __restrict__ src) {
    const long long* s64 = (const long long*)src;
    int ok = 1;
    for (int i = 0; i < 64; i++) {
        long long v = s64[i];
        if (v < 0 || v >= NN) { ok = 0; break; }
    }
    g_is64 = ok;
}

// x = relu(h); zero degrees, counters, wsum
__global__ void k_init(const float* __restrict__ h) {
    int i = blockIdx.x * blockDim.x + threadIdx.x;
    if (i < NN * FEAT) {
        g_x[i] = fmaxf(h[i], 0.0f);
    }
    if (i < NP * NN) {
        g_deg_out[i] = 0;
        g_deg_in[i]  = 0;
    }
    if (i < NP) { g_wsum[i] = 0.0f; g_ecnt[i] = 0; }
}

// index conversion (int64 or int32 -> int32, clamped) + degree histograms
__global__ void k_degcvt(const void* __restrict__ src,
                         const void* __restrict__ dst) {
    int i = blockIdx.x * blockDim.x + threadIdx.x;
    if (i >= NP * EE) return;
    int p = i / EE;
    long long sv, dv;
    if (g_is64) {
        sv = ((const long long*)src)[i];
        dv = ((const long long*)dst)[i];
    } else {
        sv = ((const int*)src)[i];
        dv = ((const int*)dst)[i];
    }
    int s = (int)sv; if (s < 0) s = 0; if (s >= NN) s = NN - 1;
    int d = (int)dv; if (d < 0) d = 0; if (d >= NN) d = NN - 1;
    g_src32[i] = s;
    g_dst32[i] = d;
    atomicAdd(&g_deg_out[p * NN + s], 1);
    atomicAdd(&g_deg_in[p * NN + d], 1);
}

// norm = clip(deg,1)^-0.5
__global__ void k_norm() {
    int i = blockIdx.x * blockDim.x + threadIdx.x;
    if (i >= NP * NN) return;
    int dOut = g_deg_out[i]; if (dOut < 1) dOut = 1;
    int dIn  = g_deg_in[i];  if (dIn  < 1) dIn  = 1;
    g_norm_out[i] = rsqrtf((float)dOut);
    g_norm_in[i]  = rsqrtf((float)dIn);
}

// CSR row offsets via atomic range grab (order within path irrelevant)
__global__ void k_rowstart() {
    int i = blockIdx.x * blockDim.x + threadIdx.x;
    if (i >= NP * NN) return;
    int p = i / NN;
    int d = g_deg_in[i];
    g_rowstart[i] = atomicAdd(&g_ecnt[p], d);
    g_fill[i] = 0;
}

// CSR fill: scatter src index into its dst row
__global__ void k_csrfill() {
    int i = blockIdx.x * blockDim.x + threadIdx.x;
    if (i >= NP * EE) return;
    int p = i / EE;
    int s = g_src32[i];
    int d = g_dst32[i];
    int idx = p * NN + d;
    int slot = atomicAdd(&g_fill[idx], 1);
    g_csr[p * EE + g_rowstart[idx] + slot] = s;
}

// fA = x * norm_out[p]  (start of each path)
__global__ void k_scale(int p) {
    int i = blockIdx.x * blockDim.x + threadIdx.x;
    if (i >= NN * FEAT) return;
    g_fA[i] = g_x[i] * g_norm_out[p * NN + (i >> 6)];
}

// gather step: one warp per node. mode 0: A->B, 1: B->A, 2: A->z[p] (last).
// acc = sum over in-edges of fin[src]; feat = 0.9*acc*norm_in + 0.1*x;
// non-last: fout = feat*norm_out (pre-scale for next step). Race-free: fin != fout.
__global__ void __launch_bounds__(256) k_gather(int p, int mode) {
    int warp = (blockIdx.x * blockDim.x + threadIdx.x) >> 5;
    if (warp >= NN) return;
    int lane = threadIdx.x & 31;
    int n = warp;
    int idx = p * NN + n;
    int start = g_rowstart[idx];
    int deg   = g_deg_in[idx];
    const int* __restrict__ csr = &g_csr[p * EE + start];
    const float2* __restrict__ fin = (mode == 1) ? (const float2*)g_fB
                                                 : (const float2*)g_fA;

    float ax = 0.0f, ay = 0.0f;
    int e = 0;
    for (; e + 4 <= deg; e += 4) {
        int s0 = csr[e], s1 = csr[e + 1], s2 = csr[e + 2], s3 = csr[e + 3];
        float2 v0 = fin[s0 * 32 + lane];
        float2 v1 = fin[s1 * 32 + lane];
        float2 v2 = fin[s2 * 32 + lane];
        float2 v3 = fin[s3 * 32 + lane];
        ax += (v0.x + v1.x) + (v2.x + v3.x);
        ay += (v0.y + v1.y) + (v2.y + v3.y);
    }
    for (; e < deg; e++) {
        float2 v = fin[csr[e] * 32 + lane];
        ax += v.x;
        ay += v.y;
    }

    float ni = g_norm_in[idx];
    float2 x = ((const float2*)g_x)[n * 32 + lane];
    float vx = 0.9f * ax * ni + ALPHA * x.x;
    float vy = 0.9f * ay * ni + ALPHA * x.y;
    if (mode == 2) {
        ((float2*)zbuf(p))[n * 32 + lane] = make_float2(vx, vy);
    } else {
        float no = g_norm_out[idx];
        float2* fout = (mode == 0) ? (float2*)g_fB : (float2*)g_fA;
        fout[n * 32 + lane] = make_float2(vx * no, vy * no);
    }
}

// semantic fusion scores: wsum[p] += sum_n tanh(z[n,p,:]@W1 + b1) @ W2
__global__ void __launch_bounds__(256) k_fusion(const float* __restrict__ W1,
                                                const float* __restrict__ b1,
                                                const float* __restrict__ W2) {
    __shared__ float sW1[FEAT * HID];   // 32 KB, row k holds W1[k][0..127]
    __shared__ float sb1[HID];
    __shared__ float sW2[HID];
    __shared__ float sred[256];
    int tid = threadIdx.x;
    for (int i = tid; i < FEAT * HID; i += 256) sW1[i] = W1[i];
    if (tid < HID) { sb1[tid] = b1[tid]; sW2[tid] = W2[tid]; }
    __syncthreads();

    int p = blockIdx.y;
    int n = blockIdx.x * 256 + tid;
    float acc = 0.0f;
    if (n < NN) {
        float zr[FEAT];
        const float4* zp = (const float4*)zbuf(p);
        #pragma unroll
        for (int i = 0; i < 16; i++) {
            float4 v = zp[n * 16 + i];
            zr[4 * i + 0] = v.x; zr[4 * i + 1] = v.y;
            zr[4 * i + 2] = v.z; zr[4 * i + 3] = v.w;
        }
        for (int j = 0; j < HID; j += 4) {
            float h0 = sb1[j], h1 = sb1[j + 1], h2 = sb1[j + 2], h3 = sb1[j + 3];
            #pragma unroll
            for (int k = 0; k < FEAT; k++) {
                float4 w = *(const float4*)&sW1[k * HID + j];
                h0 = fmaf(zr[k], w.x, h0);
                h1 = fmaf(zr[k], w.y, h1);
                h2 = fmaf(zr[k], w.z, h2);
                h3 = fmaf(zr[k], w.w, h3);
            }
            acc += tanhf(h0) * sW2[j]     + tanhf(h1) * sW2[j + 1]
                 + tanhf(h2) * sW2[j + 2] + tanhf(h3) * sW2[j + 3];
        }
    }
    sred[tid] = acc;
    __syncthreads();
    for (int s = 128; s > 0; s >>= 1) {
        if (tid < s) sred[tid] += sred[tid + s];
        __syncthreads();
    }
    if (tid == 0) atomicAdd(&g_wsum[p], sred[0]);
}

// beta = softmax(wsum / N)
__global__ void k_softmax() {
    float w0 = g_wsum[0] / (float)NN;
    float w1 = g_wsum[1] / (float)NN;
    float w2 = g_wsum[2] / (float)NN;
    float m = fmaxf(w0, fmaxf(w1, w2));
    float e0 = expf(w0 - m), e1 = expf(w1 - m), e2 = expf(w2 - m);
    float s = e0 + e1 + e2;
    g_beta[0] = e0 / s; g_beta[1] = e1 / s; g_beta[2] = e2 / s;
}

// out = sum_p beta[p] * z[p]
__global__ void k_final(float* __restrict__ out) {
    int i = blockIdx.x * blockDim.x + threadIdx.x;   // float4 granularity
    if (i >= NN * 16) return;
    float b0 = g_beta[0], b1 = g_beta[1], b2 = g_beta[2];
    float4 a = ((const float4*)g_z0)[i];
    float4 b = ((const float4*)g_z1)[i];
    float4 c = ((const float4*)g_z2)[i];
    float4 o;
    o.x = b0 * a.x + b1 * b.x + b2 * c.x;
    o.y = b0 * a.y + b1 * b.y + b2 * c.y;
    o.z = b0 * a.z + b1 * b.z + b2 * c.z;
    o.w = b0 * a.w + b1 * b.w + b2 * c.w;
    ((float4*)out)[i] = o;
}

// ---------------- launch ----------------
extern "C" void kernel_launch(void* const* d_in, const int* in_sizes, int n_in,
                              void* d_out, int out_size) {
    const float* h   = (const float*)d_in[0];
    const void*  src = d_in[1];
    const void*  dst = d_in[2];
    const float* W1  = (const float*)d_in[3];
    const float* b1  = (const float*)d_in[4];
    const float* W2  = (const float*)d_in[5];
    float* out = (float*)d_out;

    const int TB = 256;
    int gNF = (NN * FEAT + TB - 1) / TB;      // 6.4M threads
    int gE  = (NP * EE + TB - 1) / TB;        // 9.6M threads
    int gPN = (NP * NN + TB - 1) / TB;
    int gV4 = (NN * 16 + TB - 1) / TB;
    int gG  = (NN * 32 + TB - 1) / TB;        // warp per node

    k_detect<<<1, 1>>>(src);
    k_init<<<gNF, TB>>>(h);
    k_degcvt<<<gE, TB>>>(src, dst);
    k_norm<<<gPN, TB>>>();
    k_rowstart<<<gPN, TB>>>();
    k_csrfill<<<gE, TB>>>();

    for (int p = 0; p < NP; p++) {
        k_scale<<<gNF, TB>>>(p);
        // ping-pong: step0 A->B, step1 B->A, step2 (last) A->z[p]
        k_gather<<<gG, TB>>>(p, 0);
        k_gather<<<gG, TB>>>(p, 1);
        k_gather<<<gG, TB>>>(p, 2);
    }

    dim3 gF((NN + TB - 1) / TB, NP);
    k_fusion<<<gF, TB>>>(W1, b1, W2);
    k_softmax<<<1, 1>>>();
    k_final<<<gV4, TB>>>(out);
}

// round 12
// speedup vs baseline: 4.3715x; 1.2137x over previous
#include <cuda_runtime.h>
#include <cuda_bf16.h>
#include <math.h>

// Problem constants
#define NN   100000
#define FEAT 64
#define HID  128
#define EE   3200000
#define NP   3
#define ALPHA 0.1f

// ---------------- device scratch (static allocation; no cudaMalloc) ----------------
__device__ __align__(16) float g_x[NN * FEAT];      // relu(h), also feat0
__device__ __align__(16) float g_z0[NN * FEAT];     // per-path final features
__device__ __align__(16) float g_z1[NN * FEAT];
__device__ __align__(16) float g_z2[NN * FEAT];
__device__ __align__(16) float g_fA[NN * FEAT];     // ping-pong feature buffers
__device__ __align__(16) float g_fB[NN * FEAT];     //   (pre-scaled by norm_out)
__device__ int   g_csr[NP * EE];      // CSR: src indices grouped by dst
__device__ int   g_rowstart[NP * NN]; // CSR row offsets (per path)
__device__ int   g_fill[NP * NN];     // per-row fill counters
__device__ int   g_ecnt[NP];          // per-path edge counters for block-base grab
__device__ int   g_deg_out[NP * NN];
__device__ int   g_deg_in[NP * NN];
__device__ float g_norm_out[NP * NN];
__device__ float g_norm_in[NP * NN];
__device__ float g_wsum[NP];
__device__ float g_beta[NP];
__device__ int   g_is64;

__device__ __forceinline__ float* zbuf(int p) {
    return p == 0 ? g_z0 : (p == 1 ? g_z1 : g_z2);
}

__device__ __forceinline__ float tanh_fast(float x) {
    float y;
    asm("tanh.approx.f32 %0, %1;" : "=f"(y) : "f"(x));
    return y;
}

// read edge index i from src/dst handling either dtype, clamped to [0, NN)
__device__ __forceinline__ int read_idx(const void* buf, int i) {
    long long v = g_is64 ? ((const long long*)buf)[i] : (long long)((const int*)buf)[i];
    int r = (int)v;
    if (r < 0) r = 0;
    if (r >= NN) r = NN - 1;
    return r;
}

// ---------------- kernels ----------------

// Detect whether index buffers are int64 or int32.
__global__ void k_detect(const void* __restrict__ src) {
    const long long* s64 = (const long long*)src;
    int ok = 1;
    for (int i = 0; i < 64; i++) {
        long long v = s64[i];
        if (v < 0 || v >= NN) { ok = 0; break; }
    }
    g_is64 = ok;
}

// x = relu(h); zero degrees, counters, wsum
__global__ void k_init(const float* __restrict__ h) {
    int i = blockIdx.x * blockDim.x + threadIdx.x;
    if (i < NN * FEAT) {
        g_x[i] = fmaxf(h[i], 0.0f);
    }
    if (i < NP * NN) {
        g_deg_out[i] = 0;
        g_deg_in[i]  = 0;
    }
    if (i < NP) { g_wsum[i] = 0.0f; g_ecnt[i] = 0; }
}

// degree histograms straight from the input buffers
__global__ void k_deg(const void* __restrict__ src,
                      const void* __restrict__ dst) {
    int i = blockIdx.x * blockDim.x + threadIdx.x;
    if (i >= NP * EE) return;
    int p = i / EE;
    int s = read_idx(src, i);
    int d = read_idx(dst, i);
    atomicAdd(&g_deg_out[p * NN + s], 1);
    atomicAdd(&g_deg_in[p * NN + d], 1);
}

// norm = clip(deg,1)^-0.5
__global__ void k_norm() {
    int i = blockIdx.x * blockDim.x + threadIdx.x;
    if (i >= NP * NN) return;
    int dOut = g_deg_out[i]; if (dOut < 1) dOut = 1;
    int dIn  = g_deg_in[i];  if (dIn  < 1) dIn  = 1;
    g_norm_out[i] = rsqrtf((float)dOut);
    g_norm_in[i]  = rsqrtf((float)dIn);
}

// CSR row offsets via in-block scan + one atomic per block (grid.y = path)
__global__ void k_rowstart() {
    __shared__ int s[256];
    __shared__ int base;
    int p   = blockIdx.y;
    int tid = threadIdx.x;
    int n   = blockIdx.x * 256 + tid;
    int d   = (n < NN) ? g_deg_in[p * NN + n] : 0;
    s[tid] = d;
    __syncthreads();
    #pragma unroll
    for (int off = 1; off < 256; off <<= 1) {
        int v = (tid >= off) ? s[tid - off] : 0;
        __syncthreads();
        s[tid] += v;
        __syncthreads();
    }
    if (tid == 255) base = atomicAdd(&g_ecnt[p], s[255]);
    __syncthreads();
    if (n < NN) {
        g_rowstart[p * NN + n] = base + s[tid] - d;  // exclusive offset
        g_fill[p * NN + n] = 0;
    }
}

// CSR fill: scatter src index into its dst row (reads inputs directly)
__global__ void k_csrfill(const void* __restrict__ src,
                          const void* __restrict__ dst) {
    int i = blockIdx.x * blockDim.x + threadIdx.x;
    if (i >= NP * EE) return;
    int p = i / EE;
    int s = read_idx(src, i);
    int d = read_idx(dst, i);
    int idx = p * NN + d;
    int slot = atomicAdd(&g_fill[idx], 1);
    g_csr[p * EE + g_rowstart[idx] + slot] = s;
}

// fA = x * norm_out[p]  (start of each path)
__global__ void k_scale(int p) {
    int i = blockIdx.x * blockDim.x + threadIdx.x;
    if (i >= NN * FEAT) return;
    g_fA[i] = g_x[i] * g_norm_out[p * NN + (i >> 6)];
}

// gather step: one warp per node. mode 0: A->B, 1: B->A, 2: A->z[p] (last).
// acc = sum over in-edges of fin[src]; feat = 0.9*acc*norm_in + 0.1*x;
// non-last: fout = feat*norm_out (pre-scale for next step). Race-free: fin != fout.
__global__ void __launch_bounds__(256) k_gather(int p, int mode) {
    int warp = (blockIdx.x * blockDim.x + threadIdx.x) >> 5;
    if (warp >= NN) return;
    int lane = threadIdx.x & 31;
    int n = warp;
    int idx = p * NN + n;
    int start = g_rowstart[idx];
    int deg   = g_deg_in[idx];
    const int* __restrict__ csr = &g_csr[p * EE + start];
    const float2* __restrict__ fin = (mode == 1) ? (const float2*)g_fB
                                                 : (const float2*)g_fA;

    float ax = 0.0f, ay = 0.0f;
    int e = 0;
    for (; e + 4 <= deg; e += 4) {
        int s0 = csr[e], s1 = csr[e + 1], s2 = csr[e + 2], s3 = csr[e + 3];
        float2 v0 = fin[s0 * 32 + lane];
        float2 v1 = fin[s1 * 32 + lane];
        float2 v2 = fin[s2 * 32 + lane];
        float2 v3 = fin[s3 * 32 + lane];
        ax += (v0.x + v1.x) + (v2.x + v3.x);
        ay += (v0.y + v1.y) + (v2.y + v3.y);
    }
    for (; e < deg; e++) {
        float2 v = fin[csr[e] * 32 + lane];
        ax += v.x;
        ay += v.y;
    }

    float ni = g_norm_in[idx];
    float2 x = ((const float2*)g_x)[n * 32 + lane];
    float vx = 0.9f * ax * ni + ALPHA * x.x;
    float vy = 0.9f * ay * ni + ALPHA * x.y;
    if (mode == 2) {
        ((float2*)zbuf(p))[n * 32 + lane] = make_float2(vx, vy);
    } else {
        float no = g_norm_out[idx];
        float2* fout = (mode == 0) ? (float2*)g_fB : (float2*)g_fA;
        fout[n * 32 + lane] = make_float2(vx * no, vy * no);
    }
}

// semantic fusion scores: wsum[p] += sum_n tanh(z[n,p,:]@W1 + b1) @ W2
__global__ void __launch_bounds__(256) k_fusion(const float* __restrict__ W1,
                                                const float* __restrict__ b1,
                                                const float* __restrict__ W2) {
    __shared__ float sW1[FEAT * HID];   // 32 KB, row k holds W1[k][0..127]
    __shared__ float sb1[HID];
    __shared__ float sW2[HID];
    __shared__ float sred[256];
    int tid = threadIdx.x;
    for (int i = tid; i < FEAT * HID; i += 256) sW1[i] = W1[i];
    if (tid < HID) { sb1[tid] = b1[tid]; sW2[tid] = W2[tid]; }
    __syncthreads();

    int p = blockIdx.y;
    int n = blockIdx.x * 256 + tid;
    float acc = 0.0f;
    if (n < NN) {
        float zr[FEAT];
        const float4* zp = (const float4*)zbuf(p);
        #pragma unroll
        for (int i = 0; i < 16; i++) {
            float4 v = zp[n * 16 + i];
            zr[4 * i + 0] = v.x; zr[4 * i + 1] = v.y;
            zr[4 * i + 2] = v.z; zr[4 * i + 3] = v.w;
        }
        for (int j = 0; j < HID; j += 4) {
            float h0 = sb1[j], h1 = sb1[j + 1], h2 = sb1[j + 2], h3 = sb1[j + 3];
            #pragma unroll
            for (int k = 0; k < FEAT; k++) {
                float4 w = *(const float4*)&sW1[k * HID + j];
                h0 = fmaf(zr[k], w.x, h0);
                h1 = fmaf(zr[k], w.y, h1);
                h2 = fmaf(zr[k], w.z, h2);
                h3 = fmaf(zr[k], w.w, h3);
            }
            acc += tanh_fast(h0) * sW2[j]     + tanh_fast(h1) * sW2[j + 1]
                 + tanh_fast(h2) * sW2[j + 2] + tanh_fast(h3) * sW2[j + 3];
        }
    }
    sred[tid] = acc;
    __syncthreads();
    for (int s = 128; s > 0; s >>= 1) {
        if (tid < s) sred[tid] += sred[tid + s];
        __syncthreads();
    }
    if (tid == 0) atomicAdd(&g_wsum[p], sred[0]);
}

// beta = softmax(wsum / N)
__global__ void k_softmax() {
    float w0 = g_wsum[0] / (float)NN;
    float w1 = g_wsum[1] / (float)NN;
    float w2 = g_wsum[2] / (float)NN;
    float m = fmaxf(w0, fmaxf(w1, w2));
    float e0 = expf(w0 - m), e1 = expf(w1 - m), e2 = expf(w2 - m);
    float s = e0 + e1 + e2;
    g_beta[0] = e0 / s; g_beta[1] = e1 / s; g_beta[2] = e2 / s;
}

// out = sum_p beta[p] * z[p]
__global__ void k_final(float* __restrict__ out) {
    int i = blockIdx.x * blockDim.x + threadIdx.x;   // float4 granularity
    if (i >= NN * 16) return;
    float b0 = g_beta[0], b1 = g_beta[1], b2 = g_beta[2];
    float4 a = ((const float4*)g_z0)[i];
    float4 b = ((const float4*)g_z1)[i];
    float4 c = ((const float4*)g_z2)[i];
    float4 o;
    o.x = b0 * a.x + b1 * b.x + b2 * c.x;
    o.y = b0 * a.y + b1 * b.y + b2 * c.y;
    o.z = b0 * a.z + b1 * b.z + b2 * c.z;
    o.w = b0 * a.w + b1 * b.w + b2 * c.w;
    ((float4*)out)[i] = o;
}

// ---------------- launch ----------------
extern "C" void kernel_launch(void* const* d_in, const int* in_sizes, int n_in,
                              void* d_out, int out_size) {
    const float* h   = (const float*)d_in[0];
    const void*  src = d_in[1];
    const void*  dst = d_in[2];
    const float* W1  = (const float*)d_in[3];
    const float* b1  = (const float*)d_in[4];
    const float* W2  = (const float*)d_in[5];
    float* out = (float*)d_out;

    const int TB = 256;
    int gNF = (NN * FEAT + TB - 1) / TB;      // 6.4M threads
    int gE  = (NP * EE + TB - 1) / TB;        // 9.6M threads
    int gPN = (NP * NN + TB - 1) / TB;
    int gV4 = (NN * 16 + TB - 1) / TB;
    int gG  = (NN * 32 + TB - 1) / TB;        // warp per node
    dim3 gRS((NN + TB - 1) / TB, NP);         // rowstart scan per path

    k_detect<<<1, 1>>>(src);
    k_init<<<gNF, TB>>>(h);
    k_deg<<<gE, TB>>>(src, dst);
    k_norm<<<gPN, TB>>>();
    k_rowstart<<<gRS, TB>>>();
    k_csrfill<<<gE, TB>>>(src, dst);

    for (int p = 0; p < NP; p++) {
        k_scale<<<gNF, TB>>>(p);
        // ping-pong: step0 A->B, step1 B->A, step2 (last) A->z[p]
        k_gather<<<gG, TB>>>(p, 0);
        k_gather<<<gG, TB>>>(p, 1);
        k_gather<<<gG, TB>>>(p, 2);
    }

    dim3 gF((NN + TB - 1) / TB, NP);
    k_fusion<<<gF, TB>>>(W1, b1, W2);
    k_softmax<<<1, 1>>>();
    k_final<<<gV4, TB>>>(out);
}

// round 13
// speedup vs baseline: 4.7098x; 1.0774x over previous
#include <cuda_runtime.h>
#include <cuda_bf16.h>
#include <cuda_fp16.h>
#include <math.h>

// Problem constants
#define NN   100000
#define FEAT 64
#define HID  128
#define EE   3200000
#define NP   3
#define ALPHA 0.1f

// ---------------- device scratch (static allocation; no cudaMalloc) ----------------
__device__ __align__(16) float   g_x[NN * FEAT];    // relu(h), also feat0 (fp32)
__device__ __align__(16) float   g_z0[NN * FEAT];   // per-path final features (fp32)
__device__ __align__(16) float   g_z1[NN * FEAT];
__device__ __align__(16) float   g_z2[NN * FEAT];
__device__ __align__(16) __half2 g_hA[NN * 32];     // ping-pong feature buffers (fp16)
__device__ __align__(16) __half2 g_hB[NN * 32];     //   (pre-scaled by norm_out)
__device__ int   g_csr[NP * EE];      // CSR: src indices grouped by dst
__device__ int   g_rowstart[NP * NN]; // CSR row offsets (per path)
__device__ int   g_fill[NP * NN];     // per-row fill counters
__device__ int   g_ecnt[NP];          // per-path edge counters for block-base grab
__device__ int   g_deg_out[NP * NN];
__device__ int   g_deg_in[NP * NN];
__device__ float g_norm_out[NP * NN];
__device__ float g_norm_in[NP * NN];
__device__ float g_wsum[NP];
__device__ float g_beta[NP];
__device__ int   g_is64;

__device__ __forceinline__ float* zbuf(int p) {
    return p == 0 ? g_z0 : (p == 1 ? g_z1 : g_z2);
}

__device__ __forceinline__ float tanh_fast(float x) {
    float y;
    asm("tanh.approx.f32 %0, %1;" : "=f"(y) : "f"(x));
    return y;
}

// read edge index i from src/dst handling either dtype, clamped to [0, NN)
__device__ __forceinline__ int read_idx(const void* buf, int i) {
    long long v = g_is64 ? ((const long long*)buf)[i] : (long long)((const int*)buf)[i];
    int r = (int)v;
    if (r < 0) r = 0;
    if (r >= NN) r = NN - 1;
    return r;
}

// ---------------- kernels ----------------

// Detect whether index buffers are int64 or int32.
__global__ void k_detect(const void* __restrict__ src) {
    const long long* s64 = (const long long*)src;
    int ok = 1;
    for (int i = 0; i < 64; i++) {
        long long v = s64[i];
        if (v < 0 || v >= NN) { ok = 0; break; }
    }
    g_is64 = ok;
}

// x = relu(h); zero degrees, counters, wsum
__global__ void k_init(const float* __restrict__ h) {
    int i = blockIdx.x * blockDim.x + threadIdx.x;
    if (i < NN * FEAT) {
        g_x[i] = fmaxf(h[i], 0.0f);
    }
    if (i < NP * NN) {
        g_deg_out[i] = 0;
        g_deg_in[i]  = 0;
    }
    if (i < NP) { g_wsum[i] = 0.0f; g_ecnt[i] = 0; }
}

// degree histograms straight from the input buffers
__global__ void k_deg(const void* __restrict__ src,
                      const void* __restrict__ dst) {
    int i = blockIdx.x * blockDim.x + threadIdx.x;
    if (i >= NP * EE) return;
    int p = i / EE;
    int s = read_idx(src, i);
    int d = read_idx(dst, i);
    atomicAdd(&g_deg_out[p * NN + s], 1);
    atomicAdd(&g_deg_in[p * NN + d], 1);
}

// norm = clip(deg,1)^-0.5
__global__ void k_norm() {
    int i = blockIdx.x * blockDim.x + threadIdx.x;
    if (i >= NP * NN) return;
    int dOut = g_deg_out[i]; if (dOut < 1) dOut = 1;
    int dIn  = g_deg_in[i];  if (dIn  < 1) dIn  = 1;
    g_norm_out[i] = rsqrtf((float)dOut);
    g_norm_in[i]  = rsqrtf((float)dIn);
}

// CSR row offsets via in-block scan + one atomic per block (grid.y = path)
__global__ void k_rowstart() {
    __shared__ int s[256];
    __shared__ int base;
    int p   = blockIdx.y;
    int tid = threadIdx.x;
    int n   = blockIdx.x * 256 + tid;
    int d   = (n < NN) ? g_deg_in[p * NN + n] : 0;
    s[tid] = d;
    __syncthreads();
    #pragma unroll
    for (int off = 1; off < 256; off <<= 1) {
        int v = (tid >= off) ? s[tid - off] : 0;
        __syncthreads();
        s[tid] += v;
        __syncthreads();
    }
    if (tid == 255) base = atomicAdd(&g_ecnt[p], s[255]);
    __syncthreads();
    if (n < NN) {
        g_rowstart[p * NN + n] = base + s[tid] - d;  // exclusive offset
        g_fill[p * NN + n] = 0;
    }
}

// CSR fill: scatter src index into its dst row (reads inputs directly)
__global__ void k_csrfill(const void* __restrict__ src,
                          const void* __restrict__ dst) {
    int i = blockIdx.x * blockDim.x + threadIdx.x;
    if (i >= NP * EE) return;
    int p = i / EE;
    int s = read_idx(src, i);
    int d = read_idx(dst, i);
    int idx = p * NN + d;
    int slot = atomicAdd(&g_fill[idx], 1);
    g_csr[p * EE + g_rowstart[idx] + slot] = s;
}

// hA = half2(x * norm_out[p])  (start of each path)
__global__ void k_scale(int p) {
    int i = blockIdx.x * blockDim.x + threadIdx.x;   // half2 granularity: NN*32
    if (i >= NN * 32) return;
    float no = g_norm_out[p * NN + (i >> 5)];
    float2 x = ((const float2*)g_x)[i];
    g_hA[i] = __floats2half2_rn(x.x * no, x.y * no);
}

// gather step: one warp per node. mode 0: A->B, 1: B->A, 2: A->z[p] (last).
// acc(fp32) = sum over in-edges of fin[src](fp16); feat = 0.9*acc*norm_in + 0.1*x;
// non-last: fout = half2(feat*norm_out). Race-free: fin != fout.
__global__ void __launch_bounds__(256) k_gather(int p, int mode) {
    int warp = (blockIdx.x * blockDim.x + threadIdx.x) >> 5;
    if (warp >= NN) return;
    int lane = threadIdx.x & 31;
    int n = warp;
    int idx = p * NN + n;
    int start = g_rowstart[idx];
    int deg   = g_deg_in[idx];
    const int* __restrict__ csr = &g_csr[p * EE + start];
    const __half2* __restrict__ fin = (mode == 1) ? g_hB : g_hA;

    float ax = 0.0f, ay = 0.0f;
    int e = 0;
    for (; e + 4 <= deg; e += 4) {
        int s0 = csr[e], s1 = csr[e + 1], s2 = csr[e + 2], s3 = csr[e + 3];
        float2 v0 = __half22float2(fin[s0 * 32 + lane]);
        float2 v1 = __half22float2(fin[s1 * 32 + lane]);
        float2 v2 = __half22float2(fin[s2 * 32 + lane]);
        float2 v3 = __half22float2(fin[s3 * 32 + lane]);
        ax += (v0.x + v1.x) + (v2.x + v3.x);
        ay += (v0.y + v1.y) + (v2.y + v3.y);
    }
    for (; e < deg; e++) {
        float2 v = __half22float2(fin[csr[e] * 32 + lane]);
        ax += v.x;
        ay += v.y;
    }

    float ni = g_norm_in[idx];
    float2 x = ((const float2*)g_x)[n * 32 + lane];
    float vx = 0.9f * ax * ni + ALPHA * x.x;
    float vy = 0.9f * ay * ni + ALPHA * x.y;
    if (mode == 2) {
        ((float2*)zbuf(p))[n * 32 + lane] = make_float2(vx, vy);
    } else {
        float no = g_norm_out[idx];
        __half2* fout = (mode == 0) ? g_hB : g_hA;
        fout[n * 32 + lane] = __floats2half2_rn(vx * no, vy * no);
    }
}

// semantic fusion scores: wsum[p] += sum_n tanh(z[n,p,:]@W1 + b1) @ W2
__global__ void __launch_bounds__(256) k_fusion(const float* __restrict__ W1,
                                                const float* __restrict__ b1,
                                                const float* __restrict__ W2) {
    __shared__ float sW1[FEAT * HID];   // 32 KB, row k holds W1[k][0..127]
    __shared__ float sb1[HID];
    __shared__ float sW2[HID];
    __shared__ float sred[256];
    int tid = threadIdx.x;
    for (int i = tid; i < FEAT * HID; i += 256) sW1[i] = W1[i];
    if (tid < HID) { sb1[tid] = b1[tid]; sW2[tid] = W2[tid]; }
    __syncthreads();

    int p = blockIdx.y;
    int n = blockIdx.x * 256 + tid;
    float acc = 0.0f;
    if (n < NN) {
        float zr[FEAT];
        const float4* zp = (const float4*)zbuf(p);
        #pragma unroll
        for (int i = 0; i < 16; i++) {
            float4 v = zp[n * 16 + i];
            zr[4 * i + 0] = v.x; zr[4 * i + 1] = v.y;
            zr[4 * i + 2] = v.z; zr[4 * i + 3] = v.w;
        }
        for (int j = 0; j < HID; j += 4) {
            float h0 = sb1[j], h1 = sb1[j + 1], h2 = sb1[j + 2], h3 = sb1[j + 3];
            #pragma unroll
            for (int k = 0; k < FEAT; k++) {
                float4 w = *(const float4*)&sW1[k * HID + j];
                h0 = fmaf(zr[k], w.x, h0);
                h1 = fmaf(zr[k], w.y, h1);
                h2 = fmaf(zr[k], w.z, h2);
                h3 = fmaf(zr[k], w.w, h3);
            }
            acc += tanh_fast(h0) * sW2[j]     + tanh_fast(h1) * sW2[j + 1]
                 + tanh_fast(h2) * sW2[j + 2] + tanh_fast(h3) * sW2[j + 3];
        }
    }
    sred[tid] = acc;
    __syncthreads();
    for (int s = 128; s > 0; s >>= 1) {
        if (tid < s) sred[tid] += sred[tid + s];
        __syncthreads();
    }
    if (tid == 0) atomicAdd(&g_wsum[p], sred[0]);
}

// beta = softmax(wsum / N)
__global__ void k_softmax() {
    float w0 = g_wsum[0] / (float)NN;
    float w1 = g_wsum[1] / (float)NN;
    float w2 = g_wsum[2] / (float)NN;
    float m = fmaxf(w0, fmaxf(w1, w2));
    float e0 = expf(w0 - m), e1 = expf(w1 - m), e2 = expf(w2 - m);
    float s = e0 + e1 + e2;
    g_beta[0] = e0 / s; g_beta[1] = e1 / s; g_beta[2] = e2 / s;
}

// out = sum_p beta[p] * z[p]
__global__ void k_final(float* __restrict__ out) {
    int i = blockIdx.x * blockDim.x + threadIdx.x;   // float4 granularity
    if (i >= NN * 16) return;
    float b0 = g_beta[0], b1 = g_beta[1], b2 = g_beta[2];
    float4 a = ((const float4*)g_z0)[i];
    float4 b = ((const float4*)g_z1)[i];
    float4 c = ((const float4*)g_z2)[i];
    float4 o;
    o.x = b0 * a.x + b1 * b.x + b2 * c.x;
    o.y = b0 * a.y + b1 * b.y + b2 * c.y;
    o.z = b0 * a.z + b1 * b.z + b2 * c.z;
    o.w = b0 * a.w + b1 * b.w + b2 * c.w;
    ((float4*)out)[i] = o;
}

// ---------------- launch ----------------
extern "C" void kernel_launch(void* const* d_in, const int* in_sizes, int n_in,
                              void* d_out, int out_size) {
    const float* h   = (const float*)d_in[0];
    const void*  src = d_in[1];
    const void*  dst = d_in[2];
    const float* W1  = (const float*)d_in[3];
    const float* b1  = (const float*)d_in[4];
    const float* W2  = (const float*)d_in[5];
    float* out = (float*)d_out;

    const int TB = 256;
    int gNF = (NN * FEAT + TB - 1) / TB;      // 6.4M threads
    int gE  = (NP * EE + TB - 1) / TB;        // 9.6M threads
    int gPN = (NP * NN + TB - 1) / TB;
    int gV4 = (NN * 16 + TB - 1) / TB;
    int gH2 = (NN * 32 + TB - 1) / TB;        // half2 granularity
    int gG  = (NN * 32 + TB - 1) / TB;        // warp per node
    dim3 gRS((NN + TB - 1) / TB, NP);         // rowstart scan per path

    k_detect<<<1, 1>>>(src);
    k_init<<<gNF, TB>>>(h);
    k_deg<<<gE, TB>>>(src, dst);
    k_norm<<<gPN, TB>>>();
    k_rowstart<<<gRS, TB>>>();
    k_csrfill<<<gE, TB>>>(src, dst);

    for (int p = 0; p < NP; p++) {
        k_scale<<<gH2, TB>>>(p);
        // ping-pong: step0 A->B, step1 B->A, step2 (last) A->z[p]
        k_gather<<<gG, TB>>>(p, 0);
        k_gather<<<gG, TB>>>(p, 1);
        k_gather<<<gG, TB>>>(p, 2);
    }

    dim3 gF((NN + TB - 1) / TB, NP);
    k_fusion<<<gF, TB>>>(W1, b1, W2);
    k_softmax<<<1, 1>>>();
    k_final<<<gV4, TB>>>(out);
}